// round 7
// baseline (speedup 1.0000x reference)
#include <cuda_runtime.h>
#include <cuda_fp16.h>
#include <math.h>

#define NMAX 100000
#define EMAX 1600000
#define CH   128
#define HEADS 4
#define FEAT 32
#define GMAX 512
#define NEG_SLOPE 0.2f
#define BN_EPS 1e-5f
#define SCAN_CHUNK 1024

// ---------------- device scratch ----------------
__device__ __half g_hh[NMAX * CH];   // GEMM output h (fp16) — attention payload
__device__ float g_acc[NMAX * CH];   // layer1 activations (fp32, pre-BN)
__device__ float g_es [NMAX * HEADS];
__device__ float g_ed [NMAX * HEADS];
__device__ float g_z  [NMAX * FEAT];
__device__ float g_bnsum1[CH];
__device__ float g_bnsq1 [CH];
__device__ float g_bnsum2[FEAT];
__device__ float g_bnsq2 [FEAT];
__device__ float g_sc1[CH],  g_sh1[CH];
__device__ float g_sc2[FEAT], g_sh2[FEAT];
__device__ float g_pool[GMAX * FEAT];
__device__ float g_cnt [GMAX];
// CSR
__device__ int g_deg[NMAX];
__device__ int g_blocksum[128];
__device__ int g_blockoff[128];
__device__ int g_rowptr[NMAX + 1];
__device__ int g_work[NMAX];
__device__ int g_csr[EMAX];

// ---------------- helpers ----------------
__device__ __forceinline__ float lrelu(float x) { return x >= 0.f ? x : NEG_SLOPE * x; }
__device__ __forceinline__ float elu_f(float x) { return x > 0.f ? x : expm1f(x); }

__device__ __forceinline__ void red_add_v4(float* p, float4 v) {
    asm volatile("red.global.add.v4.f32 [%0], {%1,%2,%3,%4};"
                 :: "l"(p), "f"(v.x), "f"(v.y), "f"(v.z), "f"(v.w) : "memory");
}

// ---------------- zero / CSR build ----------------
__global__ void k_zero(int n) {
    int i = blockIdx.x * blockDim.x + threadIdx.x;
    if (i < n)           g_deg[i] = 0;
    if (i < GMAX * FEAT) g_pool[i] = 0.f;
    if (i < GMAX)        g_cnt[i] = 0.f;
    if (i < CH)   { g_bnsum1[i] = 0.f; g_bnsq1[i] = 0.f; }
    if (i < FEAT) { g_bnsum2[i] = 0.f; g_bnsq2[i] = 0.f; }
}

__global__ void k_hist(const int* __restrict__ dst, int E) {
    int e = blockIdx.x * blockDim.x + threadIdx.x;
    if (e < E) atomicAdd(&g_deg[dst[e]], 1);
}

// hierarchical warp-shuffle inclusive scan over 1024-chunks
__global__ void k_scan1(int n) {
    __shared__ int wsum[32];
    int t = threadIdx.x;
    int i = blockIdx.x * SCAN_CHUNK + t;
    int l = t & 31, w = t >> 5;
    int v = (i < n) ? g_deg[i] : 0;
    int x = v;
#pragma unroll
    for (int off = 1; off < 32; off <<= 1) {
        int u = __shfl_up_sync(0xffffffffu, x, off);
        if (l >= off) x += u;
    }
    if (l == 31) wsum[w] = x;
    __syncthreads();
    if (w == 0) {
        int y = wsum[l];
#pragma unroll
        for (int off = 1; off < 32; off <<= 1) {
            int u = __shfl_up_sync(0xffffffffu, y, off);
            if (l >= off) y += u;
        }
        wsum[l] = y;
    }
    __syncthreads();
    if (w > 0) x += wsum[w - 1];
    if (i < n) g_deg[i] = x;
    if (t == SCAN_CHUNK - 1) g_blocksum[blockIdx.x] = x;
}

// single-warp exclusive scan of up to 128 block sums
__global__ void k_scan2(int B) {
    int l = threadIdx.x;          // 32 threads
    int base = l * 4;
    int v0 = (base + 0 < B) ? g_blocksum[base + 0] : 0;
    int v1 = (base + 1 < B) ? g_blocksum[base + 1] : 0;
    int v2 = (base + 2 < B) ? g_blocksum[base + 2] : 0;
    int v3 = (base + 3 < B) ? g_blocksum[base + 3] : 0;
    int s1 = v0, s2 = s1 + v1, s3 = s2 + v2, s4 = s3 + v3;
    int x = s4;
#pragma unroll
    for (int off = 1; off < 32; off <<= 1) {
        int u = __shfl_up_sync(0xffffffffu, x, off);
        if (l >= off) x += u;
    }
    int ex = x - s4;
    g_blockoff[base + 0] = ex;
    g_blockoff[base + 1] = ex + s1;
    g_blockoff[base + 2] = ex + s2;
    g_blockoff[base + 3] = ex + s3;
}

__global__ void k_scan3(int n) {
    int i = blockIdx.x * blockDim.x + threadIdx.x;
    if (i > n) return;
    int val = (i == 0) ? 0 : g_deg[i - 1] + g_blockoff[(i - 1) >> 10];
    g_rowptr[i] = val;
    if (i < n) g_work[i] = val;
}

__global__ void k_scatter(const int* __restrict__ src, const int* __restrict__ dst, int E) {
    int e = blockIdx.x * blockDim.x + threadIdx.x;
    if (e >= E) return;
    int d = dst[e];
    int p = atomicAdd(&g_work[d], 1);
    g_csr[p] = src[e];
}

// ---------------- GEMM + fused act-in + es/ed epilogue; fp16 h out ----------------
template<bool ACT>
__global__ void __launch_bounds__(256, 1)
k_gemm(const float* __restrict__ X, const float* __restrict__ W,
       const float* __restrict__ sc, const float* __restrict__ sh,
       const float* __restrict__ a_src, const float* __restrict__ a_dst,
       __half* __restrict__ Y, int n) {
    extern __shared__ float sm[];
    float4* ws4 = (float4*)sm;                // [128][32] float4
    float4* xs4 = (float4*)(sm + 16384);      // [128][32] float4
    int t = threadIdx.x;
    int rb = blockIdx.x * 128;
    const float4* W4 = (const float4*)W;
    const float4* X4 = (const float4*)X;
#pragma unroll
    for (int i = 0; i < 16; i++) {
        int q = i * 256 + t;
        ws4[q] = W4[q];
        int row = q >> 5, cf = q & 31;
        float4 v = make_float4(0.f, 0.f, 0.f, 0.f);
        if (rb + row < n) v = X4[(long)(rb + row) * 32 + cf];
        if (ACT) {
            int c0 = cf * 4;
            v.x = elu_f(sc[c0 + 0] * v.x + sh[c0 + 0]);
            v.y = elu_f(sc[c0 + 1] * v.y + sh[c0 + 1]);
            v.z = elu_f(sc[c0 + 2] * v.z + sh[c0 + 2]);
            v.w = elu_f(sc[c0 + 3] * v.w + sh[c0 + 3]);
        }
        xs4[q] = v;
    }
    __syncthreads();
    int tx = t & 15, ty = t >> 4;
    int r0 = ty * 8, c0 = tx * 8;
    float acc[8][8];
#pragma unroll
    for (int r = 0; r < 8; r++)
#pragma unroll
        for (int c = 0; c < 8; c++) acc[r][c] = 0.f;

    for (int k4 = 0; k4 < 32; k4++) {
        float4 xv[8];
#pragma unroll
        for (int r = 0; r < 8; r++) xv[r] = xs4[(r0 + r) * 32 + k4];
#pragma unroll
        for (int kk = 0; kk < 4; kk++) {
            float4 w0 = ws4[(k4 * 4 + kk) * 32 + tx * 2];
            float4 w1 = ws4[(k4 * 4 + kk) * 32 + tx * 2 + 1];
#pragma unroll
            for (int r = 0; r < 8; r++) {
                const float* xvf = (const float*)&xv[r];
                float x = xvf[kk];
                acc[r][0] += x * w0.x; acc[r][1] += x * w0.y;
                acc[r][2] += x * w0.z; acc[r][3] += x * w0.w;
                acc[r][4] += x * w1.x; acc[r][5] += x * w1.y;
                acc[r][6] += x * w1.z; acc[r][7] += x * w1.w;
            }
        }
    }
    // epilogue: es/ed per head (fp32 accumulators) + fp16 store
    int head = tx >> 2;
    int cmod = (tx * 8) & 31;
    float as_[8], ad_[8];
#pragma unroll
    for (int j = 0; j < 8; j++) {
        as_[j] = a_src[head * FEAT + cmod + j];
        ad_[j] = a_dst[head * FEAT + cmod + j];
    }
#pragma unroll
    for (int r = 0; r < 8; r++) {
        float pes = 0.f, ped = 0.f;
#pragma unroll
        for (int j = 0; j < 8; j++) { pes += acc[r][j] * as_[j]; ped += acc[r][j] * ad_[j]; }
        pes += __shfl_xor_sync(0xffffffffu, pes, 1);
        pes += __shfl_xor_sync(0xffffffffu, pes, 2);
        ped += __shfl_xor_sync(0xffffffffu, ped, 1);
        ped += __shfl_xor_sync(0xffffffffu, ped, 2);
        int row = rb + r0 + r;
        if (row < n) {
            if ((tx & 3) == 0) {
                g_es[row * HEADS + head] = pes;
                g_ed[row * HEADS + head] = ped;
            }
            __half2 h0 = __floats2half2_rn(acc[r][0], acc[r][1]);
            __half2 h1 = __floats2half2_rn(acc[r][2], acc[r][3]);
            __half2 h2 = __floats2half2_rn(acc[r][4], acc[r][5]);
            __half2 h3 = __floats2half2_rn(acc[r][6], acc[r][7]);
            uint4 u;
            u.x = *(unsigned*)&h0; u.y = *(unsigned*)&h1;
            u.z = *(unsigned*)&h2; u.w = *(unsigned*)&h3;
            *(uint4*)&Y[(long)row * CH + c0] = u;
        }
    }
}

// ---------------- half-warp-per-node attention + fused finalize ----------------
// 16-lane group per dst node: lane owns 8 contiguous channels (LDG.128 gathers),
// 16-edge chunks (matches mean degree 16), group-masked syncs, 4-level reductions.
template<int LAYER>
__global__ void __launch_bounds__(256)
k_attn(const __half* __restrict__ h, const float* __restrict__ bias,
       float* __restrict__ bnsum, float* __restrict__ bnsq,
       int n, int ngroups) {
    __shared__ int   s_idx[16][16];
    __shared__ float s_w  [16][64];
    int tid = threadIdx.x;
    int grp = tid >> 4;                   // 0..15 within block
    int l16 = tid & 15;
    unsigned gmask = 0xFFFFu << ((grp & 1) * 16);
    int gw = blockIdx.x * 16 + grp;
    int headq = l16 >> 2;                 // head for this lane's channels
    int c8 = l16 * 8;                     // first of 8 channels owned
    float bs[8], bq[8];
#pragma unroll
    for (int i = 0; i < 8; i++) { bs[i] = 0.f; bq[i] = 0.f; }

    for (int d = gw; d < n; d += ngroups) {
        int beg = g_rowptr[d], end = g_rowptr[d + 1];
        float4 ed4 = *(const float4*)&g_ed[d * HEADS];
        float4 esd = *(const float4*)&g_es[d * HEADS];
        float4 wsf;
        wsf.x = __expf(lrelu(esd.x + ed4.x));
        wsf.y = __expf(lrelu(esd.y + ed4.y));
        wsf.z = __expf(lrelu(esd.z + ed4.z));
        wsf.w = __expf(lrelu(esd.w + ed4.w));
        float wsh = headq == 0 ? wsf.x : headq == 1 ? wsf.y : headq == 2 ? wsf.z : wsf.w;
        float facc[8];
        {   // self-loop init: 16B load = 8 fp16 channels
            uint4 raw = *(const uint4*)&h[(long)d * CH + c8];
            float2 f0 = __half22float2(*(__half2*)&raw.x);
            float2 f1 = __half22float2(*(__half2*)&raw.y);
            float2 f2 = __half22float2(*(__half2*)&raw.z);
            float2 f3 = __half22float2(*(__half2*)&raw.w);
            facc[0] = wsh * f0.x; facc[1] = wsh * f0.y;
            facc[2] = wsh * f1.x; facc[3] = wsh * f1.y;
            facc[4] = wsh * f2.x; facc[5] = wsh * f2.y;
            facc[6] = wsh * f3.x; facc[7] = wsh * f3.y;
        }
        float4 den = (l16 == 0) ? wsf : make_float4(0.f, 0.f, 0.f, 0.f);

        for (int j0 = beg; j0 < end; j0 += 16) {
            int j = j0 + l16;
            int s = 0;
            float4 w4 = make_float4(0.f, 0.f, 0.f, 0.f);
            if (j < end) {
                s = g_csr[j];
                float4 es4 = *(const float4*)&g_es[s * HEADS];
                w4.x = __expf(lrelu(es4.x + ed4.x));
                w4.y = __expf(lrelu(es4.y + ed4.y));
                w4.z = __expf(lrelu(es4.z + ed4.z));
                w4.w = __expf(lrelu(es4.w + ed4.w));
            }
            den.x += w4.x; den.y += w4.y; den.z += w4.z; den.w += w4.w;
            s_idx[grp][l16] = s;
            *(float4*)&s_w[grp][l16 * 4] = w4;
            __syncwarp(gmask);
            int kmax = min(16, end - j0);
#pragma unroll 4
            for (int k = 0; k < kmax; k++) {
                int   sk = s_idx[grp][k];
                float w  = s_w[grp][k * 4 + headq];
                uint4 raw = *(const uint4*)&h[(long)sk * CH + c8];
                float2 f0 = __half22float2(*(__half2*)&raw.x);
                float2 f1 = __half22float2(*(__half2*)&raw.y);
                float2 f2 = __half22float2(*(__half2*)&raw.z);
                float2 f3 = __half22float2(*(__half2*)&raw.w);
                facc[0] += w * f0.x; facc[1] += w * f0.y;
                facc[2] += w * f1.x; facc[3] += w * f1.y;
                facc[4] += w * f2.x; facc[5] += w * f2.y;
                facc[6] += w * f3.x; facc[7] += w * f3.y;
            }
            __syncwarp(gmask);
        }
        // den reduce within the 16-lane group
#pragma unroll
        for (int o = 1; o <= 8; o <<= 1) {
            den.x += __shfl_xor_sync(gmask, den.x, o);
            den.y += __shfl_xor_sync(gmask, den.y, o);
            den.z += __shfl_xor_sync(gmask, den.z, o);
            den.w += __shfl_xor_sync(gmask, den.w, o);
        }
        float dh = headq == 0 ? den.x : headq == 1 ? den.y : headq == 2 ? den.z : den.w;
        float rd = 1.f / dh;
        if (LAYER == 1) {
            float v[8];
#pragma unroll
            for (int i = 0; i < 8; i++) {
                v[i] = facc[i] * rd + bias[c8 + i];
                bs[i] += v[i]; bq[i] += v[i] * v[i];
            }
            *(float4*)&g_acc[(long)d * CH + c8]     = make_float4(v[0], v[1], v[2], v[3]);
            *(float4*)&g_acc[(long)d * CH + c8 + 4] = make_float4(v[4], v[5], v[6], v[7]);
        } else {
            float v[8];
#pragma unroll
            for (int i = 0; i < 8; i++) v[i] = facc[i] * rd;
            // head-sum: lanes l16, l16^4, l16^8 share f = (l16&3)*8 + i
#pragma unroll
            for (int i = 0; i < 8; i++) {
                v[i] += __shfl_xor_sync(gmask, v[i], 4);
                v[i] += __shfl_xor_sync(gmask, v[i], 8);
            }
            if (l16 < 4) {
                int f8 = l16 * 8;
#pragma unroll
                for (int i = 0; i < 8; i++) {
                    v[i] = 0.25f * v[i] + bias[f8 + i];
                    bs[i] += v[i]; bq[i] += v[i] * v[i];
                }
                *(float4*)&g_z[(long)d * FEAT + f8]     = make_float4(v[0], v[1], v[2], v[3]);
                *(float4*)&g_z[(long)d * FEAT + f8 + 4] = make_float4(v[4], v[5], v[6], v[7]);
            }
        }
    }
    // flush BN stats: combine the two groups of the warp (same channel map), then flush
    __syncwarp();
#pragma unroll
    for (int i = 0; i < 8; i++) {
        bs[i] += __shfl_xor_sync(0xffffffffu, bs[i], 16);
        bq[i] += __shfl_xor_sync(0xffffffffu, bq[i], 16);
    }
    if ((tid & 16) == 0 && (LAYER == 1 || l16 < 4)) {
        int c0 = (LAYER == 1) ? c8 : l16 * 8;
#pragma unroll
        for (int j = 0; j < 8; j++) {
            atomicAdd(&bnsum[c0 + j], bs[j]);
            atomicAdd(&bnsq [c0 + j], bq[j]);
        }
    }
}

// ---------------- BN scale/shift prep ----------------
__global__ void k_bnprep(const float* __restrict__ gamma, const float* __restrict__ beta,
                         const float* __restrict__ bnsum, const float* __restrict__ bnsq,
                         float* __restrict__ sc, float* __restrict__ sh,
                         int C, float inv_n) {
    int c = threadIdx.x;
    if (c >= C) return;
    float mean = bnsum[c] * inv_n;
    float var  = bnsq[c] * inv_n - mean * mean;
    float g = gamma[c] * rsqrtf(var + BN_EPS);
    sc[c] = g;
    sh[c] = beta[c] - mean * g;
}

// ---------------- pool with fused BN+ELU ----------------
__global__ void k_pool(const int* __restrict__ batch, int n) {
    int i = blockIdx.x * blockDim.x + threadIdx.x;
    if (i >= n) return;
    int g = batch[i];
    const float4* zp = (const float4*)&g_z[(long)i * FEAT];
#pragma unroll
    for (int c = 0; c < 8; c++) {
        float4 z = zp[c];
        int c0 = c * 4;
        z.x = elu_f(g_sc2[c0 + 0] * z.x + g_sh2[c0 + 0]);
        z.y = elu_f(g_sc2[c0 + 1] * z.y + g_sh2[c0 + 1]);
        z.z = elu_f(g_sc2[c0 + 2] * z.z + g_sh2[c0 + 2]);
        z.w = elu_f(g_sc2[c0 + 3] * z.w + g_sh2[c0 + 3]);
        red_add_v4(&g_pool[g * FEAT + c0], z);
    }
    atomicAdd(&g_cnt[g], 1.f);
}

__global__ void k_final(const float* __restrict__ Wl, const float* __restrict__ bl,
                        float* __restrict__ out, int G) {
    int idx = blockIdx.x * blockDim.x + threadIdx.x;
    if (idx >= G * 2) return;
    int g = idx >> 1, o = idx & 1;
    float cn = fmaxf(g_cnt[g], 1.f);
    float s = bl[o];
#pragma unroll
    for (int f = 0; f < FEAT; f++)
        s += (g_pool[g * FEAT + f] / cn) * Wl[f * 2 + o];
    out[idx] = s;
}

// ---------------- host launch ----------------
extern "C" void kernel_launch(void* const* d_in, const int* in_sizes, int n_in,
                              void* d_out, int out_size) {
    const float* x   = (const float*)d_in[0];
    const int*   ei  = (const int*)  d_in[1];
    const int*   bat = (const int*)  d_in[2];
    const float* W1  = (const float*)d_in[3];
    const float* as1 = (const float*)d_in[4];
    const float* ad1 = (const float*)d_in[5];
    const float* b1  = (const float*)d_in[6];
    const float* g1  = (const float*)d_in[7];
    const float* be1 = (const float*)d_in[8];
    const float* W2  = (const float*)d_in[9];
    const float* as2 = (const float*)d_in[10];
    const float* ad2 = (const float*)d_in[11];
    const float* b2  = (const float*)d_in[12];
    const float* g2  = (const float*)d_in[13];
    const float* be2 = (const float*)d_in[14];
    const float* Wl  = (const float*)d_in[15];
    const float* bl  = (const float*)d_in[16];
    float* out = (float*)d_out;

    int n = in_sizes[0] / CH;   // 100000
    int E = in_sizes[1] / 2;    // 1600000
    int G = out_size / 2;       // 512
    const int* esrc = ei;
    const int* edst = ei + E;

    static __half* phh = nullptr;
    static float *pacc;
    static float *psc1, *psh1, *psc2, *psh2;
    static float *pbs1, *pbq1, *pbs2, *pbq2;
    static cudaStream_t s2;
    static cudaEvent_t ev_fork, ev_join;
    static bool configured = false;
    if (!configured) {
        cudaGetSymbolAddress((void**)&phh,  g_hh);
        cudaGetSymbolAddress((void**)&pacc, g_acc);
        cudaGetSymbolAddress((void**)&psc1, g_sc1);
        cudaGetSymbolAddress((void**)&psh1, g_sh1);
        cudaGetSymbolAddress((void**)&psc2, g_sc2);
        cudaGetSymbolAddress((void**)&psh2, g_sh2);
        cudaGetSymbolAddress((void**)&pbs1, g_bnsum1);
        cudaGetSymbolAddress((void**)&pbq1, g_bnsq1);
        cudaGetSymbolAddress((void**)&pbs2, g_bnsum2);
        cudaGetSymbolAddress((void**)&pbq2, g_bnsq2);
        cudaFuncSetAttribute(k_gemm<false>, cudaFuncAttributeMaxDynamicSharedMemorySize,
                             2 * 128 * 128 * sizeof(float));
        cudaFuncSetAttribute(k_gemm<true>, cudaFuncAttributeMaxDynamicSharedMemorySize,
                             2 * 128 * 128 * sizeof(float));
        cudaStreamCreateWithFlags(&s2, cudaStreamNonBlocking);
        cudaEventCreateWithFlags(&ev_fork, cudaEventDisableTiming);
        cudaEventCreateWithFlags(&ev_join, cudaEventDisableTiming);
        configured = true;
    }

    float inv_n = 1.f / (float)n;
    int nb_node = (n + 255) / 256;
    int nb_edge = (E + 255) / 256;
    int nb_gemm = (n + 127) / 128;
    int nb_attn = 592;
    int ngroups = nb_attn * 16;            // 16-lane groups
    int B_scan  = (n + SCAN_CHUNK - 1) / SCAN_CHUNK;
    size_t gsmem = 2 * 128 * 128 * sizeof(float);

    // zero, then fork: CSR build on s2 || GEMM-1 on main stream
    k_zero<<<nb_node, 256>>>(n);
    cudaEventRecord(ev_fork, 0);
    cudaStreamWaitEvent(s2, ev_fork, 0);
    k_hist   <<<nb_edge, 256, 0, s2>>>(edst, E);
    k_scan1  <<<B_scan, SCAN_CHUNK, 0, s2>>>(n);
    k_scan2  <<<1, 32, 0, s2>>>(B_scan);
    k_scan3  <<<(n + 256) / 256, 256, 0, s2>>>(n);
    k_scatter<<<nb_edge, 256, 0, s2>>>(esrc, edst, E);
    cudaEventRecord(ev_join, s2);

    // ---- layer 1 ----
    k_gemm<false><<<nb_gemm, 256, gsmem>>>(x, W1, nullptr, nullptr, as1, ad1, phh, n);
    cudaStreamWaitEvent(0, ev_join, 0);
    k_attn<1><<<nb_attn, 256>>>(phh, b1, pbs1, pbq1, n, ngroups);
    k_bnprep<<<1, CH>>>(g1, be1, pbs1, pbq1, psc1, psh1, CH, inv_n);

    // ---- layer 2 (BN+ELU of layer1 fused into GEMM load) ----
    k_gemm<true><<<nb_gemm, 256, gsmem>>>(pacc, W2, psc1, psh1, as2, ad2, phh, n);
    k_attn<2><<<nb_attn, 256>>>(phh, b2, pbs2, pbq2, n, ngroups);
    k_bnprep<<<1, FEAT>>>(g2, be2, pbs2, pbq2, psc2, psh2, FEAT, inv_n);

    // ---- pool (BN+ELU fused) + linear ----
    k_pool<<<nb_node, 256>>>(bat, n);
    k_final<<<(G * 2 + 255) / 256, 256>>>(Wl, bl, out, G);
}

// round 8
// speedup vs baseline: 1.1549x; 1.1549x over previous
#include <cuda_runtime.h>
#include <cuda_fp16.h>
#include <math.h>

#define NMAX 100000
#define EMAX 1600000
#define CH   128
#define HEADS 4
#define FEAT 32
#define GMAX 512
#define NEG_SLOPE 0.2f
#define BN_EPS 1e-5f
#define SCAN_CHUNK 1024

// ---------------- device scratch ----------------
__device__ __half g_hh[NMAX * CH];   // GEMM output h (fp16) — attention payload
__device__ float g_acc[NMAX * CH];   // layer1 activations (fp32, pre-BN)
__device__ float g_es [NMAX * HEADS];
__device__ float g_ed [NMAX * HEADS];
__device__ float g_z  [NMAX * FEAT];
__device__ float g_bnsum1[CH];
__device__ float g_bnsq1 [CH];
__device__ float g_bnsum2[FEAT];
__device__ float g_bnsq2 [FEAT];
__device__ float g_sc1[CH],  g_sh1[CH];
__device__ float g_sc2[FEAT], g_sh2[FEAT];
__device__ float g_pool[GMAX * FEAT];
__device__ float g_cnt [GMAX];
// CSR
__device__ int g_deg[NMAX];
__device__ int g_blocksum[128];
__device__ int g_blockoff[128];
__device__ int g_rowptr[NMAX + 1];
__device__ int g_work[NMAX];
__device__ int g_csr[EMAX];

// ---------------- helpers ----------------
__device__ __forceinline__ float lrelu(float x) { return x >= 0.f ? x : NEG_SLOPE * x; }
__device__ __forceinline__ float elu_f(float x) { return x > 0.f ? x : expm1f(x); }

__device__ __forceinline__ void red_add_v4(float* p, float4 v) {
    asm volatile("red.global.add.v4.f32 [%0], {%1,%2,%3,%4};"
                 :: "l"(p), "f"(v.x), "f"(v.y), "f"(v.z), "f"(v.w) : "memory");
}

__device__ __forceinline__ unsigned f2tf32(float v) {
    unsigned u;
    asm("cvt.rna.tf32.f32 %0, %1;" : "=r"(u) : "f"(v));
    return u;
}

// load 4 consecutive halfs as float4 (8B load)
__device__ __forceinline__ float4 ld_h4(const __half* p) {
    uint2 raw = *(const uint2*)p;
    float2 fa = __half22float2(*(__half2*)&raw.x);
    float2 fb = __half22float2(*(__half2*)&raw.y);
    return make_float4(fa.x, fa.y, fb.x, fb.y);
}

// ---------------- zero / CSR build ----------------
__global__ void k_zero(int n) {
    int i = blockIdx.x * blockDim.x + threadIdx.x;
    if (i < n)           g_deg[i] = 0;
    if (i < GMAX * FEAT) g_pool[i] = 0.f;
    if (i < GMAX)        g_cnt[i] = 0.f;
    if (i < CH)   { g_bnsum1[i] = 0.f; g_bnsq1[i] = 0.f; }
    if (i < FEAT) { g_bnsum2[i] = 0.f; g_bnsq2[i] = 0.f; }
}

__global__ void k_hist(const int* __restrict__ dst, int E) {
    int e = blockIdx.x * blockDim.x + threadIdx.x;
    if (e < E) atomicAdd(&g_deg[dst[e]], 1);
}

__global__ void k_scan1(int n) {
    __shared__ int wsum[32];
    int t = threadIdx.x;
    int i = blockIdx.x * SCAN_CHUNK + t;
    int l = t & 31, w = t >> 5;
    int v = (i < n) ? g_deg[i] : 0;
    int x = v;
#pragma unroll
    for (int off = 1; off < 32; off <<= 1) {
        int u = __shfl_up_sync(0xffffffffu, x, off);
        if (l >= off) x += u;
    }
    if (l == 31) wsum[w] = x;
    __syncthreads();
    if (w == 0) {
        int y = wsum[l];
#pragma unroll
        for (int off = 1; off < 32; off <<= 1) {
            int u = __shfl_up_sync(0xffffffffu, y, off);
            if (l >= off) y += u;
        }
        wsum[l] = y;
    }
    __syncthreads();
    if (w > 0) x += wsum[w - 1];
    if (i < n) g_deg[i] = x;
    if (t == SCAN_CHUNK - 1) g_blocksum[blockIdx.x] = x;
}

__global__ void k_scan2(int B) {
    int l = threadIdx.x;          // 32 threads
    int base = l * 4;
    int v0 = (base + 0 < B) ? g_blocksum[base + 0] : 0;
    int v1 = (base + 1 < B) ? g_blocksum[base + 1] : 0;
    int v2 = (base + 2 < B) ? g_blocksum[base + 2] : 0;
    int v3 = (base + 3 < B) ? g_blocksum[base + 3] : 0;
    int s1 = v0, s2 = s1 + v1, s3 = s2 + v2, s4 = s3 + v3;
    int x = s4;
#pragma unroll
    for (int off = 1; off < 32; off <<= 1) {
        int u = __shfl_up_sync(0xffffffffu, x, off);
        if (l >= off) x += u;
    }
    int ex = x - s4;
    g_blockoff[base + 0] = ex;
    g_blockoff[base + 1] = ex + s1;
    g_blockoff[base + 2] = ex + s2;
    g_blockoff[base + 3] = ex + s3;
}

__global__ void k_scan3(int n) {
    int i = blockIdx.x * blockDim.x + threadIdx.x;
    if (i > n) return;
    int val = (i == 0) ? 0 : g_deg[i - 1] + g_blockoff[(i - 1) >> 10];
    g_rowptr[i] = val;
    if (i < n) g_work[i] = val;
}

__global__ void k_scatter(const int* __restrict__ src, const int* __restrict__ dst, int E) {
    int e = blockIdx.x * blockDim.x + threadIdx.x;
    if (e >= E) return;
    int d = dst[e];
    int p = atomicAdd(&g_work[d], 1);
    g_csr[p] = src[e];
}

// ---------------- tf32 MMA GEMM + fused act-in + es/ed epilogue; fp16 h out ----------------
// Block: 256 thr (8 warps), tile 128 rows x 128 cols, K=128.
// smem: A frags (64KB) + B frags (64KB) pre-permuted in mma fragment order,
// + a_src/a_dst copies (1KB). Warp w computes rows w*16..w*16+15, all 128 cols.
template<bool ACT>
__global__ void __launch_bounds__(256, 1)
k_gemm(const float* __restrict__ X, const float* __restrict__ W,
       const float* __restrict__ sc, const float* __restrict__ sh,
       const float* __restrict__ a_src, const float* __restrict__ a_dst,
       __half* __restrict__ Y, int n) {
    extern __shared__ float smf[];
    unsigned* a_buf = (unsigned*)smf;              // 16384 u32
    unsigned* b_buf = a_buf + 16384;               // 16384 u32
    float*    s_as  = (float*)(b_buf + 16384);     // 128
    float*    s_ad  = s_as + 128;                  // 128
    int t = threadIdx.x;
    int rb = blockIdx.x * 128;
    const float4* X4 = (const float4*)X;
    const float4* W4 = (const float4*)W;

    if (t < 128) { s_as[t] = a_src[t]; s_ad[t] = a_dst[t]; }

    // load X -> a_buf (fragment-permuted, ACT fused, tf32-rounded)
#pragma unroll
    for (int i = 0; i < 16; i++) {
        int q = i * 256 + t;                 // 0..4095 float4s
        int row = q >> 5, c4 = (q & 31) * 4;
        float4 v = make_float4(0.f, 0.f, 0.f, 0.f);
        if (rb + row < n) v = X4[(long)(rb + row) * 32 + (q & 31)];
        if (ACT) {
            v.x = elu_f(sc[c4 + 0] * v.x + sh[c4 + 0]);
            v.y = elu_f(sc[c4 + 1] * v.y + sh[c4 + 1]);
            v.z = elu_f(sc[c4 + 2] * v.z + sh[c4 + 2]);
            v.w = elu_f(sc[c4 + 3] * v.w + sh[c4 + 3]);
        }
        const float* vf = (const float*)&v;
#pragma unroll
        for (int e = 0; e < 4; e++) {
            int col = c4 + e;
            int j = ((row & 15) >= 8 ? 1 : 0) | ((col & 7) >= 4 ? 2 : 0);
            int l = ((row & 7) << 2) | (col & 3);
            int idx = (((row >> 4) << 4) + (col >> 3)) * 128 + l * 4 + j;
            a_buf[idx] = f2tf32(vf[e]);
        }
    }
    // load W -> b_buf (fragment-permuted, tf32-rounded)
#pragma unroll
    for (int i = 0; i < 16; i++) {
        int q = i * 256 + t;
        int k = q >> 5, c4 = (q & 31) * 4;
        float4 v = W4[q];
        const float* vf = (const float*)&v;
#pragma unroll
        for (int e = 0; e < 4; e++) {
            int ncol = c4 + e;
            int j = (k & 7) >= 4 ? 1 : 0;
            int l = ((ncol & 7) << 2) | (k & 3);
            int idx = ((k >> 3) * 16 + (ncol >> 3)) * 64 + l * 2 + j;
            b_buf[idx] = f2tf32(vf[e]);
        }
    }
    __syncthreads();

    int w = t >> 5, l = t & 31;
    float d[16][4];
#pragma unroll
    for (int nb = 0; nb < 16; nb++)
#pragma unroll
        for (int j = 0; j < 4; j++) d[nb][j] = 0.f;

    const uint4* a4 = (const uint4*)a_buf;
    const uint2* b2 = (const uint2*)b_buf;
    for (int kb = 0; kb < 16; kb++) {
        uint4 a = a4[(w * 16 + kb) * 32 + l];
#pragma unroll
        for (int nb = 0; nb < 16; nb++) {
            uint2 b = b2[(kb * 16 + nb) * 32 + l];
            asm volatile(
                "mma.sync.aligned.m16n8k8.row.col.f32.tf32.tf32.f32 "
                "{%0,%1,%2,%3}, {%4,%5,%6,%7}, {%8,%9}, {%0,%1,%2,%3};"
                : "+f"(d[nb][0]), "+f"(d[nb][1]), "+f"(d[nb][2]), "+f"(d[nb][3])
                : "r"(a.x), "r"(a.y), "r"(a.z), "r"(a.w), "r"(b.x), "r"(b.y));
        }
    }

    // epilogue. Fragment: lane holds rows r0=w*16+l/4, r1=r0+8; cols nb*8+(l%4)*2+{0,1}.
    int r0g = rb + w * 16 + (l >> 2);
    int r1g = r0g + 8;
    int cb0 = (l & 3) * 2;
    float es0[4], es1[4], ed0[4], ed1[4];
#pragma unroll
    for (int hh = 0; hh < 4; hh++) { es0[hh] = 0.f; es1[hh] = 0.f; ed0[hh] = 0.f; ed1[hh] = 0.f; }
#pragma unroll
    for (int nb = 0; nb < 16; nb++) {
        int colb = nb * 8 + cb0;
        int hh = nb >> 2;
        float a0 = s_as[colb], a1 = s_as[colb + 1];
        float b0 = s_ad[colb], b1 = s_ad[colb + 1];
        es0[hh] += d[nb][0] * a0 + d[nb][1] * a1;
        es1[hh] += d[nb][2] * a0 + d[nb][3] * a1;
        ed0[hh] += d[nb][0] * b0 + d[nb][1] * b1;
        ed1[hh] += d[nb][2] * b0 + d[nb][3] * b1;
    }
#pragma unroll
    for (int o = 1; o <= 2; o <<= 1) {
#pragma unroll
        for (int hh = 0; hh < 4; hh++) {
            es0[hh] += __shfl_xor_sync(0xffffffffu, es0[hh], o);
            es1[hh] += __shfl_xor_sync(0xffffffffu, es1[hh], o);
            ed0[hh] += __shfl_xor_sync(0xffffffffu, ed0[hh], o);
            ed1[hh] += __shfl_xor_sync(0xffffffffu, ed1[hh], o);
        }
    }
    if ((l & 3) == 0) {
        if (r0g < n) {
            *(float4*)&g_es[r0g * HEADS] = make_float4(es0[0], es0[1], es0[2], es0[3]);
            *(float4*)&g_ed[r0g * HEADS] = make_float4(ed0[0], ed0[1], ed0[2], ed0[3]);
        }
        if (r1g < n) {
            *(float4*)&g_es[r1g * HEADS] = make_float4(es1[0], es1[1], es1[2], es1[3]);
            *(float4*)&g_ed[r1g * HEADS] = make_float4(ed1[0], ed1[1], ed1[2], ed1[3]);
        }
    }
    // fp16 stores
    bool st0 = r0g < n, st1 = r1g < n;
#pragma unroll
    for (int nb = 0; nb < 16; nb++) {
        int colb = nb * 8 + cb0;
        if (st0) {
            __half2 hv = __floats2half2_rn(d[nb][0], d[nb][1]);
            *(unsigned*)&Y[(long)r0g * CH + colb] = *(unsigned*)&hv;
        }
        if (st1) {
            __half2 hv = __floats2half2_rn(d[nb][2], d[nb][3]);
            *(unsigned*)&Y[(long)r1g * CH + colb] = *(unsigned*)&hv;
        }
    }
}

// ---------------- persistent warp-per-dst attention + fused finalize (R6 version) ----------------
template<int LAYER>
__global__ void __launch_bounds__(256)
k_attn(const __half* __restrict__ h, const float* __restrict__ bias,
       float* __restrict__ bnsum, float* __restrict__ bnsq,
       int n, int nwarps) {
    __shared__ int   s_idx[8][32];
    __shared__ float s_w  [8][128];
    int wb = threadIdx.x >> 5, l = threadIdx.x & 31;
    int gw = blockIdx.x * 8 + wb;
    int hsel = l >> 3, cg = l * 4;
    float bs[4] = {0.f, 0.f, 0.f, 0.f};
    float bq[4] = {0.f, 0.f, 0.f, 0.f};

    for (int d = gw; d < n; d += nwarps) {
        int beg = g_rowptr[d], end = g_rowptr[d + 1];
        float4 ed4 = *(const float4*)&g_ed[d * HEADS];
        float4 esd = *(const float4*)&g_es[d * HEADS];
        float4 wsf;
        wsf.x = __expf(lrelu(esd.x + ed4.x));
        wsf.y = __expf(lrelu(esd.y + ed4.y));
        wsf.z = __expf(lrelu(esd.z + ed4.z));
        wsf.w = __expf(lrelu(esd.w + ed4.w));
        float wsh = hsel == 0 ? wsf.x : hsel == 1 ? wsf.y : hsel == 2 ? wsf.z : wsf.w;
        float4 acc = ld_h4(&h[(long)d * CH + cg]);
        acc.x *= wsh; acc.y *= wsh; acc.z *= wsh; acc.w *= wsh;
        float4 den = (l == 0) ? wsf : make_float4(0.f, 0.f, 0.f, 0.f);

        for (int j0 = beg; j0 < end; j0 += 32) {
            int j = j0 + l;
            int s = 0;
            float4 w4 = make_float4(0.f, 0.f, 0.f, 0.f);
            if (j < end) {
                s = g_csr[j];
                float4 es4 = *(const float4*)&g_es[s * HEADS];
                w4.x = __expf(lrelu(es4.x + ed4.x));
                w4.y = __expf(lrelu(es4.y + ed4.y));
                w4.z = __expf(lrelu(es4.z + ed4.z));
                w4.w = __expf(lrelu(es4.w + ed4.w));
            }
            den.x += w4.x; den.y += w4.y; den.z += w4.z; den.w += w4.w;
            s_idx[wb][l] = s;
            *(float4*)&s_w[wb][l * 4] = w4;
            __syncwarp();
            int kmax = min(32, end - j0);
#pragma unroll 4
            for (int k = 0; k < kmax; k++) {
                int   sk = s_idx[wb][k];
                float w  = s_w[wb][k * 4 + hsel];
                float4 hv = ld_h4(&h[(long)sk * CH + cg]);
                acc.x += w * hv.x; acc.y += w * hv.y;
                acc.z += w * hv.z; acc.w += w * hv.w;
            }
            __syncwarp();
        }
#pragma unroll
        for (int o = 16; o; o >>= 1) {
            den.x += __shfl_xor_sync(0xffffffffu, den.x, o);
            den.y += __shfl_xor_sync(0xffffffffu, den.y, o);
            den.z += __shfl_xor_sync(0xffffffffu, den.z, o);
            den.w += __shfl_xor_sync(0xffffffffu, den.w, o);
        }
        float dh = hsel == 0 ? den.x : hsel == 1 ? den.y : hsel == 2 ? den.z : den.w;
        float rd = 1.f / dh;
        if (LAYER == 1) {
            float4 b4 = *(const float4*)&bias[cg];
            float4 v;
            v.x = acc.x * rd + b4.x; v.y = acc.y * rd + b4.y;
            v.z = acc.z * rd + b4.z; v.w = acc.w * rd + b4.w;
            *(float4*)&g_acc[(long)d * CH + cg] = v;
            bs[0] += v.x; bs[1] += v.y; bs[2] += v.z; bs[3] += v.w;
            bq[0] += v.x * v.x; bq[1] += v.y * v.y; bq[2] += v.z * v.z; bq[3] += v.w * v.w;
        } else {
            float4 v;
            v.x = acc.x * rd; v.y = acc.y * rd; v.z = acc.z * rd; v.w = acc.w * rd;
#pragma unroll
            for (int o = 8; o <= 16; o <<= 1) {
                v.x += __shfl_xor_sync(0xffffffffu, v.x, o);
                v.y += __shfl_xor_sync(0xffffffffu, v.y, o);
                v.z += __shfl_xor_sync(0xffffffffu, v.z, o);
                v.w += __shfl_xor_sync(0xffffffffu, v.w, o);
            }
            if (l < 8) {
                float4 b4 = *(const float4*)&bias[l * 4];
                v.x = 0.25f * v.x + b4.x; v.y = 0.25f * v.y + b4.y;
                v.z = 0.25f * v.z + b4.z; v.w = 0.25f * v.w + b4.w;
                *(float4*)&g_z[(long)d * FEAT + l * 4] = v;
                bs[0] += v.x; bs[1] += v.y; bs[2] += v.z; bs[3] += v.w;
                bq[0] += v.x * v.x; bq[1] += v.y * v.y; bq[2] += v.z * v.z; bq[3] += v.w * v.w;
            }
        }
    }
    if (LAYER == 1 || l < 8) {
        int c0 = (LAYER == 1) ? cg : l * 4;
#pragma unroll
        for (int j = 0; j < 4; j++) {
            atomicAdd(&bnsum[c0 + j], bs[j]);
            atomicAdd(&bnsq [c0 + j], bq[j]);
        }
    }
}

// ---------------- BN scale/shift prep ----------------
__global__ void k_bnprep(const float* __restrict__ gamma, const float* __restrict__ beta,
                         const float* __restrict__ bnsum, const float* __restrict__ bnsq,
                         float* __restrict__ sc, float* __restrict__ sh,
                         int C, float inv_n) {
    int c = threadIdx.x;
    if (c >= C) return;
    float mean = bnsum[c] * inv_n;
    float var  = bnsq[c] * inv_n - mean * mean;
    float g = gamma[c] * rsqrtf(var + BN_EPS);
    sc[c] = g;
    sh[c] = beta[c] - mean * g;
}

// ---------------- pool with fused BN+ELU ----------------
__global__ void k_pool(const int* __restrict__ batch, int n) {
    int i = blockIdx.x * blockDim.x + threadIdx.x;
    if (i >= n) return;
    int g = batch[i];
    const float4* zp = (const float4*)&g_z[(long)i * FEAT];
#pragma unroll
    for (int c = 0; c < 8; c++) {
        float4 z = zp[c];
        int c0 = c * 4;
        z.x = elu_f(g_sc2[c0 + 0] * z.x + g_sh2[c0 + 0]);
        z.y = elu_f(g_sc2[c0 + 1] * z.y + g_sh2[c0 + 1]);
        z.z = elu_f(g_sc2[c0 + 2] * z.z + g_sh2[c0 + 2]);
        z.w = elu_f(g_sc2[c0 + 3] * z.w + g_sh2[c0 + 3]);
        red_add_v4(&g_pool[g * FEAT + c0], z);
    }
    atomicAdd(&g_cnt[g], 1.f);
}

__global__ void k_final(const float* __restrict__ Wl, const float* __restrict__ bl,
                        float* __restrict__ out, int G) {
    int idx = blockIdx.x * blockDim.x + threadIdx.x;
    if (idx >= G * 2) return;
    int g = idx >> 1, o = idx & 1;
    float cn = fmaxf(g_cnt[g], 1.f);
    float s = bl[o];
#pragma unroll
    for (int f = 0; f < FEAT; f++)
        s += (g_pool[g * FEAT + f] / cn) * Wl[f * 2 + o];
    out[idx] = s;
}

// ---------------- host launch ----------------
extern "C" void kernel_launch(void* const* d_in, const int* in_sizes, int n_in,
                              void* d_out, int out_size) {
    const float* x   = (const float*)d_in[0];
    const int*   ei  = (const int*)  d_in[1];
    const int*   bat = (const int*)  d_in[2];
    const float* W1  = (const float*)d_in[3];
    const float* as1 = (const float*)d_in[4];
    const float* ad1 = (const float*)d_in[5];
    const float* b1  = (const float*)d_in[6];
    const float* g1  = (const float*)d_in[7];
    const float* be1 = (const float*)d_in[8];
    const float* W2  = (const float*)d_in[9];
    const float* as2 = (const float*)d_in[10];
    const float* ad2 = (const float*)d_in[11];
    const float* b2  = (const float*)d_in[12];
    const float* g2  = (const float*)d_in[13];
    const float* be2 = (const float*)d_in[14];
    const float* Wl  = (const float*)d_in[15];
    const float* bl  = (const float*)d_in[16];
    float* out = (float*)d_out;

    int n = in_sizes[0] / CH;   // 100000
    int E = in_sizes[1] / 2;    // 1600000
    int G = out_size / 2;       // 512
    const int* esrc = ei;
    const int* edst = ei + E;

    static __half* phh = nullptr;
    static float *pacc;
    static float *psc1, *psh1, *psc2, *psh2;
    static float *pbs1, *pbq1, *pbs2, *pbq2;
    static cudaStream_t s2;
    static cudaEvent_t ev_fork, ev_join;
    static bool configured = false;
    size_t gsmem = 2 * 16384 * sizeof(unsigned) + 256 * sizeof(float);  // 132 KB
    if (!configured) {
        cudaGetSymbolAddress((void**)&phh,  g_hh);
        cudaGetSymbolAddress((void**)&pacc, g_acc);
        cudaGetSymbolAddress((void**)&psc1, g_sc1);
        cudaGetSymbolAddress((void**)&psh1, g_sh1);
        cudaGetSymbolAddress((void**)&psc2, g_sc2);
        cudaGetSymbolAddress((void**)&psh2, g_sh2);
        cudaGetSymbolAddress((void**)&pbs1, g_bnsum1);
        cudaGetSymbolAddress((void**)&pbq1, g_bnsq1);
        cudaGetSymbolAddress((void**)&pbs2, g_bnsum2);
        cudaGetSymbolAddress((void**)&pbq2, g_bnsq2);
        cudaFuncSetAttribute(k_gemm<false>, cudaFuncAttributeMaxDynamicSharedMemorySize, (int)gsmem);
        cudaFuncSetAttribute(k_gemm<true>,  cudaFuncAttributeMaxDynamicSharedMemorySize, (int)gsmem);
        cudaStreamCreateWithFlags(&s2, cudaStreamNonBlocking);
        cudaEventCreateWithFlags(&ev_fork, cudaEventDisableTiming);
        cudaEventCreateWithFlags(&ev_join, cudaEventDisableTiming);
        configured = true;
    }

    float inv_n = 1.f / (float)n;
    int nb_node = (n + 255) / 256;
    int nb_edge = (E + 255) / 256;
    int nb_gemm = (n + 127) / 128;
    int nb_attn = 592;
    int nwarps  = nb_attn * 8;
    int B_scan  = (n + SCAN_CHUNK - 1) / SCAN_CHUNK;

    // zero, then fork: CSR build on s2 || GEMM-1 on main stream
    k_zero<<<nb_node, 256>>>(n);
    cudaEventRecord(ev_fork, 0);
    cudaStreamWaitEvent(s2, ev_fork, 0);
    k_hist   <<<nb_edge, 256, 0, s2>>>(edst, E);
    k_scan1  <<<B_scan, SCAN_CHUNK, 0, s2>>>(n);
    k_scan2  <<<1, 32, 0, s2>>>(B_scan);
    k_scan3  <<<(n + 256) / 256, 256, 0, s2>>>(n);
    k_scatter<<<nb_edge, 256, 0, s2>>>(esrc, edst, E);
    cudaEventRecord(ev_join, s2);

    // ---- layer 1 ----
    k_gemm<false><<<nb_gemm, 256, gsmem>>>(x, W1, nullptr, nullptr, as1, ad1, phh, n);
    cudaStreamWaitEvent(0, ev_join, 0);
    k_attn<1><<<nb_attn, 256>>>(phh, b1, pbs1, pbq1, n, nwarps);
    k_bnprep<<<1, CH>>>(g1, be1, pbs1, pbq1, psc1, psh1, CH, inv_n);

    // ---- layer 2 (BN+ELU of layer1 fused into GEMM load) ----
    k_gemm<true><<<nb_gemm, 256, gsmem>>>(pacc, W2, psc1, psh1, as2, ad2, phh, n);
    k_attn<2><<<nb_attn, 256>>>(phh, b2, pbs2, pbq2, n, nwarps);
    k_bnprep<<<1, FEAT>>>(g2, be2, pbs2, pbq2, psc2, psh2, FEAT, inv_n);

    // ---- pool (BN+ELU fused) + linear ----
    k_pool<<<nb_node, 256>>>(bat, n);
    k_final<<<(G * 2 + 255) / 256, 256>>>(Wl, bl, out, G);
}

// round 9
// speedup vs baseline: 1.4407x; 1.2475x over previous
#include <cuda_runtime.h>
#include <cuda_fp16.h>
#include <math.h>

#define NMAX 100000
#define EMAX 1600000
#define CH   128
#define HEADS 4
#define FEAT 32
#define GMAX 512
#define NEG_SLOPE 0.2f
#define BN_EPS 1e-5f
#define SCAN_CHUNK 1024
#define A_STR 132   // padded row stride (floats) for A smem: banks (4*gr+gc)%32 all distinct

// ---------------- device scratch ----------------
__device__ __half g_hh[NMAX * CH];   // GEMM output h (fp16) — attention payload
__device__ float g_acc[NMAX * CH];   // layer1 activations (fp32, pre-BN)
__device__ float g_es [NMAX * HEADS];
__device__ float g_ed [NMAX * HEADS];
__device__ float g_z  [NMAX * FEAT];
__device__ float g_bnsum1[CH];
__device__ float g_bnsq1 [CH];
__device__ float g_bnsum2[FEAT];
__device__ float g_bnsq2 [FEAT];
__device__ float g_sc1[CH],  g_sh1[CH];
__device__ float g_sc2[FEAT], g_sh2[FEAT];
__device__ float g_pool[GMAX * FEAT];
__device__ float g_cnt [GMAX];
// CSR
__device__ int g_deg[NMAX];
__device__ int g_blocksum[128];
__device__ int g_blockoff[128];
__device__ int g_rowptr[NMAX + 1];
__device__ int g_work[NMAX];
__device__ int g_csr[EMAX];

// ---------------- helpers ----------------
__device__ __forceinline__ float lrelu(float x) { return x >= 0.f ? x : NEG_SLOPE * x; }
__device__ __forceinline__ float elu_f(float x) { return x > 0.f ? x : expm1f(x); }

__device__ __forceinline__ void red_add_v4(float* p, float4 v) {
    asm volatile("red.global.add.v4.f32 [%0], {%1,%2,%3,%4};"
                 :: "l"(p), "f"(v.x), "f"(v.y), "f"(v.z), "f"(v.w) : "memory");
}

__device__ __forceinline__ unsigned f2tf32(float v) {
    unsigned u;
    asm("cvt.rna.tf32.f32 %0, %1;" : "=r"(u) : "f"(v));
    return u;
}

// load 4 consecutive halfs as float4 (8B load)
__device__ __forceinline__ float4 ld_h4(const __half* p) {
    uint2 raw = *(const uint2*)p;
    float2 fa = __half22float2(*(__half2*)&raw.x);
    float2 fb = __half22float2(*(__half2*)&raw.y);
    return make_float4(fa.x, fa.y, fb.x, fb.y);
}

// ---------------- zero / CSR build ----------------
__global__ void k_zero(int n) {
    int i = blockIdx.x * blockDim.x + threadIdx.x;
    if (i < n)           g_deg[i] = 0;
    if (i < GMAX * FEAT) g_pool[i] = 0.f;
    if (i < GMAX)        g_cnt[i] = 0.f;
    if (i < CH)   { g_bnsum1[i] = 0.f; g_bnsq1[i] = 0.f; }
    if (i < FEAT) { g_bnsum2[i] = 0.f; g_bnsq2[i] = 0.f; }
}

__global__ void k_hist(const int* __restrict__ dst, int E) {
    int e = blockIdx.x * blockDim.x + threadIdx.x;
    if (e < E) atomicAdd(&g_deg[dst[e]], 1);
}

__global__ void k_scan1(int n) {
    __shared__ int wsum[32];
    int t = threadIdx.x;
    int i = blockIdx.x * SCAN_CHUNK + t;
    int l = t & 31, w = t >> 5;
    int v = (i < n) ? g_deg[i] : 0;
    int x = v;
#pragma unroll
    for (int off = 1; off < 32; off <<= 1) {
        int u = __shfl_up_sync(0xffffffffu, x, off);
        if (l >= off) x += u;
    }
    if (l == 31) wsum[w] = x;
    __syncthreads();
    if (w == 0) {
        int y = wsum[l];
#pragma unroll
        for (int off = 1; off < 32; off <<= 1) {
            int u = __shfl_up_sync(0xffffffffu, y, off);
            if (l >= off) y += u;
        }
        wsum[l] = y;
    }
    __syncthreads();
    if (w > 0) x += wsum[w - 1];
    if (i < n) g_deg[i] = x;
    if (t == SCAN_CHUNK - 1) g_blocksum[blockIdx.x] = x;
}

__global__ void k_scan2(int B) {
    int l = threadIdx.x;          // 32 threads
    int base = l * 4;
    int v0 = (base + 0 < B) ? g_blocksum[base + 0] : 0;
    int v1 = (base + 1 < B) ? g_blocksum[base + 1] : 0;
    int v2 = (base + 2 < B) ? g_blocksum[base + 2] : 0;
    int v3 = (base + 3 < B) ? g_blocksum[base + 3] : 0;
    int s1 = v0, s2 = s1 + v1, s3 = s2 + v2, s4 = s3 + v3;
    int x = s4;
#pragma unroll
    for (int off = 1; off < 32; off <<= 1) {
        int u = __shfl_up_sync(0xffffffffu, x, off);
        if (l >= off) x += u;
    }
    int ex = x - s4;
    g_blockoff[base + 0] = ex;
    g_blockoff[base + 1] = ex + s1;
    g_blockoff[base + 2] = ex + s2;
    g_blockoff[base + 3] = ex + s3;
}

__global__ void k_scan3(int n) {
    int i = blockIdx.x * blockDim.x + threadIdx.x;
    if (i > n) return;
    int val = (i == 0) ? 0 : g_deg[i - 1] + g_blockoff[(i - 1) >> 10];
    g_rowptr[i] = val;
    if (i < n) g_work[i] = val;
}

__global__ void k_scatter(const int* __restrict__ src, const int* __restrict__ dst, int E) {
    int e = blockIdx.x * blockDim.x + threadIdx.x;
    if (e >= E) return;
    int d = dst[e];
    int p = atomicAdd(&g_work[d], 1);
    g_csr[p] = src[e];
}

// ---------------- tf32 MMA GEMM v2: conflict-free smem, fused act-in + es/ed epilogue ----------------
// A: row-major smem, stride A_STR (pad) -> STS.128 coalesced, fragment LDS.32 conflict-free.
// B: fragment-permuted uint2 with XOR swizzle (store 2-way, load conflict-free LDS.64).
template<bool ACT>
__global__ void __launch_bounds__(256, 1)
k_gemm(const float* __restrict__ X, const float* __restrict__ W,
       const float* __restrict__ sc, const float* __restrict__ sh,
       const float* __restrict__ a_src, const float* __restrict__ a_dst,
       __half* __restrict__ Y, int n) {
    extern __shared__ float smf[];
    float*    a_s   = smf;                         // 128 * A_STR floats (tf32 bits as float)
    unsigned* b_buf = (unsigned*)(smf + 128 * A_STR);  // 16384 u32
    float*    s_as  = (float*)(b_buf + 16384);     // 128
    float*    s_ad  = s_as + 128;                  // 128
    int t = threadIdx.x;
    int rb = blockIdx.x * 128;
    const float4* X4 = (const float4*)X;
    const float4* W4 = (const float4*)W;

    if (t < 128) { s_as[t] = a_src[t]; s_ad[t] = a_dst[t]; }

    // load X -> a_s row-major padded (ACT fused, tf32-rounded). STS.128 conflict-free.
#pragma unroll
    for (int i = 0; i < 16; i++) {
        int q = i * 256 + t;                 // 0..4095 float4s
        int row = q >> 5, c4 = (q & 31) * 4;
        float4 v = make_float4(0.f, 0.f, 0.f, 0.f);
        if (rb + row < n) v = X4[(long)(rb + row) * 32 + (q & 31)];
        if (ACT) {
            v.x = elu_f(sc[c4 + 0] * v.x + sh[c4 + 0]);
            v.y = elu_f(sc[c4 + 1] * v.y + sh[c4 + 1]);
            v.z = elu_f(sc[c4 + 2] * v.z + sh[c4 + 2]);
            v.w = elu_f(sc[c4 + 3] * v.w + sh[c4 + 3]);
        }
        float4 tv;
        tv.x = __uint_as_float(f2tf32(v.x));
        tv.y = __uint_as_float(f2tf32(v.y));
        tv.z = __uint_as_float(f2tf32(v.z));
        tv.w = __uint_as_float(f2tf32(v.w));
        *(float4*)&a_s[row * A_STR + c4] = tv;
    }
    // load W -> b_buf fragment-permuted + XOR swizzle (tf32-rounded)
#pragma unroll
    for (int i = 0; i < 16; i++) {
        int q = i * 256 + t;
        int k = q >> 5, c4 = (q & 31) * 4;
        float4 v = W4[q];
        const float* vf = (const float*)&v;
#pragma unroll
        for (int e = 0; e < 4; e++) {
            int ncol = c4 + e;
            int tile = (k >> 3) * 16 + (ncol >> 3);
            int lf = ((ncol & 7) << 2) | (k & 3);
            int j = (k & 7) >= 4 ? 1 : 0;
            int off = (lf * 2 + j) ^ ((tile & 15) << 1);
            b_buf[tile * 64 + off] = f2tf32(vf[e]);
        }
    }
    __syncthreads();

    int w = t >> 5, l = t & 31;
    int gr = l >> 2, gc = l & 3;
    float d[16][4];
#pragma unroll
    for (int nb = 0; nb < 16; nb++)
#pragma unroll
        for (int j = 0; j < 4; j++) d[nb][j] = 0.f;

    int arow = (w * 16 + gr) * A_STR + gc;
    for (int kb = 0; kb < 16; kb++) {
        int ab = arow + kb * 8;
        unsigned a0 = __float_as_uint(a_s[ab]);
        unsigned a1 = __float_as_uint(a_s[ab + 8 * A_STR]);
        unsigned a2 = __float_as_uint(a_s[ab + 4]);
        unsigned a3 = __float_as_uint(a_s[ab + 8 * A_STR + 4]);
#pragma unroll
        for (int nb = 0; nb < 16; nb++) {
            int tile = kb * 16 + nb;
            uint2 b = *(const uint2*)&b_buf[tile * 64 + ((l * 2) ^ (nb << 1))];
            asm volatile(
                "mma.sync.aligned.m16n8k8.row.col.f32.tf32.tf32.f32 "
                "{%0,%1,%2,%3}, {%4,%5,%6,%7}, {%8,%9}, {%0,%1,%2,%3};"
                : "+f"(d[nb][0]), "+f"(d[nb][1]), "+f"(d[nb][2]), "+f"(d[nb][3])
                : "r"(a0), "r"(a1), "r"(a2), "r"(a3), "r"(b.x), "r"(b.y));
        }
    }

    // epilogue. Fragment: lane holds rows r0=w*16+l/4, r1=r0+8; cols nb*8+(l%4)*2+{0,1}.
    int r0g = rb + w * 16 + gr;
    int r1g = r0g + 8;
    int cb0 = gc * 2;
    float es0[4], es1[4], ed0[4], ed1[4];
#pragma unroll
    for (int hh = 0; hh < 4; hh++) { es0[hh] = 0.f; es1[hh] = 0.f; ed0[hh] = 0.f; ed1[hh] = 0.f; }
#pragma unroll
    for (int nb = 0; nb < 16; nb++) {
        int colb = nb * 8 + cb0;
        int hh = nb >> 2;
        float a0 = s_as[colb], a1 = s_as[colb + 1];
        float b0 = s_ad[colb], b1 = s_ad[colb + 1];
        es0[hh] += d[nb][0] * a0 + d[nb][1] * a1;
        es1[hh] += d[nb][2] * a0 + d[nb][3] * a1;
        ed0[hh] += d[nb][0] * b0 + d[nb][1] * b1;
        ed1[hh] += d[nb][2] * b0 + d[nb][3] * b1;
    }
#pragma unroll
    for (int o = 1; o <= 2; o <<= 1) {
#pragma unroll
        for (int hh = 0; hh < 4; hh++) {
            es0[hh] += __shfl_xor_sync(0xffffffffu, es0[hh], o);
            es1[hh] += __shfl_xor_sync(0xffffffffu, es1[hh], o);
            ed0[hh] += __shfl_xor_sync(0xffffffffu, ed0[hh], o);
            ed1[hh] += __shfl_xor_sync(0xffffffffu, ed1[hh], o);
        }
    }
    if (gc == 0) {
        if (r0g < n) {
            *(float4*)&g_es[r0g * HEADS] = make_float4(es0[0], es0[1], es0[2], es0[3]);
            *(float4*)&g_ed[r0g * HEADS] = make_float4(ed0[0], ed0[1], ed0[2], ed0[3]);
        }
        if (r1g < n) {
            *(float4*)&g_es[r1g * HEADS] = make_float4(es1[0], es1[1], es1[2], es1[3]);
            *(float4*)&g_ed[r1g * HEADS] = make_float4(ed1[0], ed1[1], ed1[2], ed1[3]);
        }
    }
    // fp16 stores
    bool st0 = r0g < n, st1 = r1g < n;
#pragma unroll
    for (int nb = 0; nb < 16; nb++) {
        int colb = nb * 8 + cb0;
        if (st0) {
            __half2 hv = __floats2half2_rn(d[nb][0], d[nb][1]);
            *(unsigned*)&Y[(long)r0g * CH + colb] = *(unsigned*)&hv;
        }
        if (st1) {
            __half2 hv = __floats2half2_rn(d[nb][2], d[nb][3]);
            *(unsigned*)&Y[(long)r1g * CH + colb] = *(unsigned*)&hv;
        }
    }
}

// ---------------- persistent warp-per-dst attention + fused finalize (R6 version) ----------------
template<int LAYER>
__global__ void __launch_bounds__(256)
k_attn(const __half* __restrict__ h, const float* __restrict__ bias,
       float* __restrict__ bnsum, float* __restrict__ bnsq,
       int n, int nwarps) {
    __shared__ int   s_idx[8][32];
    __shared__ float s_w  [8][128];
    int wb = threadIdx.x >> 5, l = threadIdx.x & 31;
    int gw = blockIdx.x * 8 + wb;
    int hsel = l >> 3, cg = l * 4;
    float bs[4] = {0.f, 0.f, 0.f, 0.f};
    float bq[4] = {0.f, 0.f, 0.f, 0.f};

    for (int d = gw; d < n; d += nwarps) {
        int beg = g_rowptr[d], end = g_rowptr[d + 1];
        float4 ed4 = *(const float4*)&g_ed[d * HEADS];
        float4 esd = *(const float4*)&g_es[d * HEADS];
        float4 wsf;
        wsf.x = __expf(lrelu(esd.x + ed4.x));
        wsf.y = __expf(lrelu(esd.y + ed4.y));
        wsf.z = __expf(lrelu(esd.z + ed4.z));
        wsf.w = __expf(lrelu(esd.w + ed4.w));
        float wsh = hsel == 0 ? wsf.x : hsel == 1 ? wsf.y : hsel == 2 ? wsf.z : wsf.w;
        float4 acc = ld_h4(&h[(long)d * CH + cg]);
        acc.x *= wsh; acc.y *= wsh; acc.z *= wsh; acc.w *= wsh;
        float4 den = (l == 0) ? wsf : make_float4(0.f, 0.f, 0.f, 0.f);

        for (int j0 = beg; j0 < end; j0 += 32) {
            int j = j0 + l;
            int s = 0;
            float4 w4 = make_float4(0.f, 0.f, 0.f, 0.f);
            if (j < end) {
                s = g_csr[j];
                float4 es4 = *(const float4*)&g_es[s * HEADS];
                w4.x = __expf(lrelu(es4.x + ed4.x));
                w4.y = __expf(lrelu(es4.y + ed4.y));
                w4.z = __expf(lrelu(es4.z + ed4.z));
                w4.w = __expf(lrelu(es4.w + ed4.w));
            }
            den.x += w4.x; den.y += w4.y; den.z += w4.z; den.w += w4.w;
            s_idx[wb][l] = s;
            *(float4*)&s_w[wb][l * 4] = w4;
            __syncwarp();
            int kmax = min(32, end - j0);
#pragma unroll 4
            for (int k = 0; k < kmax; k++) {
                int   sk = s_idx[wb][k];
                float w  = s_w[wb][k * 4 + hsel];
                float4 hv = ld_h4(&h[(long)sk * CH + cg]);
                acc.x += w * hv.x; acc.y += w * hv.y;
                acc.z += w * hv.z; acc.w += w * hv.w;
            }
            __syncwarp();
        }
#pragma unroll
        for (int o = 16; o; o >>= 1) {
            den.x += __shfl_xor_sync(0xffffffffu, den.x, o);
            den.y += __shfl_xor_sync(0xffffffffu, den.y, o);
            den.z += __shfl_xor_sync(0xffffffffu, den.z, o);
            den.w += __shfl_xor_sync(0xffffffffu, den.w, o);
        }
        float dh = hsel == 0 ? den.x : hsel == 1 ? den.y : hsel == 2 ? den.z : den.w;
        float rd = 1.f / dh;
        if (LAYER == 1) {
            float4 b4 = *(const float4*)&bias[cg];
            float4 v;
            v.x = acc.x * rd + b4.x; v.y = acc.y * rd + b4.y;
            v.z = acc.z * rd + b4.z; v.w = acc.w * rd + b4.w;
            *(float4*)&g_acc[(long)d * CH + cg] = v;
            bs[0] += v.x; bs[1] += v.y; bs[2] += v.z; bs[3] += v.w;
            bq[0] += v.x * v.x; bq[1] += v.y * v.y; bq[2] += v.z * v.z; bq[3] += v.w * v.w;
        } else {
            float4 v;
            v.x = acc.x * rd; v.y = acc.y * rd; v.z = acc.z * rd; v.w = acc.w * rd;
#pragma unroll
            for (int o = 8; o <= 16; o <<= 1) {
                v.x += __shfl_xor_sync(0xffffffffu, v.x, o);
                v.y += __shfl_xor_sync(0xffffffffu, v.y, o);
                v.z += __shfl_xor_sync(0xffffffffu, v.z, o);
                v.w += __shfl_xor_sync(0xffffffffu, v.w, o);
            }
            if (l < 8) {
                float4 b4 = *(const float4*)&bias[l * 4];
                v.x = 0.25f * v.x + b4.x; v.y = 0.25f * v.y + b4.y;
                v.z = 0.25f * v.z + b4.z; v.w = 0.25f * v.w + b4.w;
                *(float4*)&g_z[(long)d * FEAT + l * 4] = v;
                bs[0] += v.x; bs[1] += v.y; bs[2] += v.z; bs[3] += v.w;
                bq[0] += v.x * v.x; bq[1] += v.y * v.y; bq[2] += v.z * v.z; bq[3] += v.w * v.w;
            }
        }
    }
    if (LAYER == 1 || l < 8) {
        int c0 = (LAYER == 1) ? cg : l * 4;
#pragma unroll
        for (int j = 0; j < 4; j++) {
            atomicAdd(&bnsum[c0 + j], bs[j]);
            atomicAdd(&bnsq [c0 + j], bq[j]);
        }
    }
}

// ---------------- BN scale/shift prep ----------------
__global__ void k_bnprep(const float* __restrict__ gamma, const float* __restrict__ beta,
                         const float* __restrict__ bnsum, const float* __restrict__ bnsq,
                         float* __restrict__ sc, float* __restrict__ sh,
                         int C, float inv_n) {
    int c = threadIdx.x;
    if (c >= C) return;
    float mean = bnsum[c] * inv_n;
    float var  = bnsq[c] * inv_n - mean * mean;
    float g = gamma[c] * rsqrtf(var + BN_EPS);
    sc[c] = g;
    sh[c] = beta[c] - mean * g;
}

// ---------------- pool with fused BN+ELU ----------------
__global__ void k_pool(const int* __restrict__ batch, int n) {
    int i = blockIdx.x * blockDim.x + threadIdx.x;
    if (i >= n) return;
    int g = batch[i];
    const float4* zp = (const float4*)&g_z[(long)i * FEAT];
#pragma unroll
    for (int c = 0; c < 8; c++) {
        float4 z = zp[c];
        int c0 = c * 4;
        z.x = elu_f(g_sc2[c0 + 0] * z.x + g_sh2[c0 + 0]);
        z.y = elu_f(g_sc2[c0 + 1] * z.y + g_sh2[c0 + 1]);
        z.z = elu_f(g_sc2[c0 + 2] * z.z + g_sh2[c0 + 2]);
        z.w = elu_f(g_sc2[c0 + 3] * z.w + g_sh2[c0 + 3]);
        red_add_v4(&g_pool[g * FEAT + c0], z);
    }
    atomicAdd(&g_cnt[g], 1.f);
}

__global__ void k_final(const float* __restrict__ Wl, const float* __restrict__ bl,
                        float* __restrict__ out, int G) {
    int idx = blockIdx.x * blockDim.x + threadIdx.x;
    if (idx >= G * 2) return;
    int g = idx >> 1, o = idx & 1;
    float cn = fmaxf(g_cnt[g], 1.f);
    float s = bl[o];
#pragma unroll
    for (int f = 0; f < FEAT; f++)
        s += (g_pool[g * FEAT + f] / cn) * Wl[f * 2 + o];
    out[idx] = s;
}

// ---------------- host launch ----------------
extern "C" void kernel_launch(void* const* d_in, const int* in_sizes, int n_in,
                              void* d_out, int out_size) {
    const float* x   = (const float*)d_in[0];
    const int*   ei  = (const int*)  d_in[1];
    const int*   bat = (const int*)  d_in[2];
    const float* W1  = (const float*)d_in[3];
    const float* as1 = (const float*)d_in[4];
    const float* ad1 = (const float*)d_in[5];
    const float* b1  = (const float*)d_in[6];
    const float* g1  = (const float*)d_in[7];
    const float* be1 = (const float*)d_in[8];
    const float* W2  = (const float*)d_in[9];
    const float* as2 = (const float*)d_in[10];
    const float* ad2 = (const float*)d_in[11];
    const float* b2  = (const float*)d_in[12];
    const float* g2  = (const float*)d_in[13];
    const float* be2 = (const float*)d_in[14];
    const float* Wl  = (const float*)d_in[15];
    const float* bl  = (const float*)d_in[16];
    float* out = (float*)d_out;

    int n = in_sizes[0] / CH;   // 100000
    int E = in_sizes[1] / 2;    // 1600000
    int G = out_size / 2;       // 512
    const int* esrc = ei;
    const int* edst = ei + E;

    static __half* phh = nullptr;
    static float *pacc;
    static float *psc1, *psh1, *psc2, *psh2;
    static float *pbs1, *pbq1, *pbs2, *pbq2;
    static cudaStream_t s2;
    static cudaEvent_t ev_fork, ev_join;
    static bool configured = false;
    size_t gsmem = (size_t)128 * A_STR * 4 + 16384 * 4 + 256 * 4;  // ~134 KB
    if (!configured) {
        cudaGetSymbolAddress((void**)&phh,  g_hh);
        cudaGetSymbolAddress((void**)&pacc, g_acc);
        cudaGetSymbolAddress((void**)&psc1, g_sc1);
        cudaGetSymbolAddress((void**)&psh1, g_sh1);
        cudaGetSymbolAddress((void**)&psc2, g_sc2);
        cudaGetSymbolAddress((void**)&psh2, g_sh2);
        cudaGetSymbolAddress((void**)&pbs1, g_bnsum1);
        cudaGetSymbolAddress((void**)&pbq1, g_bnsq1);
        cudaGetSymbolAddress((void**)&pbs2, g_bnsum2);
        cudaGetSymbolAddress((void**)&pbq2, g_bnsq2);
        cudaFuncSetAttribute(k_gemm<false>, cudaFuncAttributeMaxDynamicSharedMemorySize, (int)gsmem);
        cudaFuncSetAttribute(k_gemm<true>,  cudaFuncAttributeMaxDynamicSharedMemorySize, (int)gsmem);
        cudaStreamCreateWithFlags(&s2, cudaStreamNonBlocking);
        cudaEventCreateWithFlags(&ev_fork, cudaEventDisableTiming);
        cudaEventCreateWithFlags(&ev_join, cudaEventDisableTiming);
        configured = true;
    }

    float inv_n = 1.f / (float)n;
    int nb_node = (n + 255) / 256;
    int nb_edge = (E + 255) / 256;
    int nb_gemm = (n + 127) / 128;
    int nb_attn = 592;
    int nwarps  = nb_attn * 8;
    int B_scan  = (n + SCAN_CHUNK - 1) / SCAN_CHUNK;

    // zero, then fork: CSR build on s2 || GEMM-1 on main stream
    k_zero<<<nb_node, 256>>>(n);
    cudaEventRecord(ev_fork, 0);
    cudaStreamWaitEvent(s2, ev_fork, 0);
    k_hist   <<<nb_edge, 256, 0, s2>>>(edst, E);
    k_scan1  <<<B_scan, SCAN_CHUNK, 0, s2>>>(n);
    k_scan2  <<<1, 32, 0, s2>>>(B_scan);
    k_scan3  <<<(n + 256) / 256, 256, 0, s2>>>(n);
    k_scatter<<<nb_edge, 256, 0, s2>>>(esrc, edst, E);
    cudaEventRecord(ev_join, s2);

    // ---- layer 1 ----
    k_gemm<false><<<nb_gemm, 256, gsmem>>>(x, W1, nullptr, nullptr, as1, ad1, phh, n);
    cudaStreamWaitEvent(0, ev_join, 0);
    k_attn<1><<<nb_attn, 256>>>(phh, b1, pbs1, pbq1, n, nwarps);
    k_bnprep<<<1, CH>>>(g1, be1, pbs1, pbq1, psc1, psh1, CH, inv_n);

    // ---- layer 2 (BN+ELU of layer1 fused into GEMM load) ----
    k_gemm<true><<<nb_gemm, 256, gsmem>>>(pacc, W2, psc1, psh1, as2, ad2, phh, n);
    k_attn<2><<<nb_attn, 256>>>(phh, b2, pbs2, pbq2, n, nwarps);
    k_bnprep<<<1, FEAT>>>(g2, be2, pbs2, pbq2, psc2, psh2, FEAT, inv_n);

    // ---- pool (BN+ELU fused) + linear ----
    k_pool<<<nb_node, 256>>>(bat, n);
    k_final<<<(G * 2 + 255) / 256, 256>>>(Wl, bl, out, G);
}